// round 14
// baseline (speedup 1.0000x reference)
#include <cuda_runtime.h>
#include <cuda_bf16.h>
#include <math_constants.h>

#define ROW    131     // 3 coords + 128 features
#define DIMF   128
#define KNN    8
#define MAXSLOTS 12    // cnt up to 384 (actual max ~256+5sigma)
#define EPSW   1e-16f
#define NBATCH 1024
#define NMAX   32768
#define INFKEY 0x7F800000u

__device__ double   g_acc;
__device__ unsigned g_done = 0;           // self-resetting via atomicInc wrap
__device__ int      g_bstart[NBATCH + 1];
__device__ float4   g_c1[NMAX];           // (x, y, z, |c|^2)

__device__ __forceinline__ unsigned redux_min_u32(unsigned v) {
    unsigned r;
    asm("redux.sync.min.u32 %0, %1, 0xffffffff;" : "=r"(r) : "r"(v));
    return r;
}

// Prep: zero accumulator, batch-start table by boundary detection,
// float4 coord repack with precomputed squared norm in .w.
__global__ __launch_bounds__(256) void prep_kernel(
    const float* __restrict__ x1, const int* __restrict__ b1, int n)
{
    const int t = blockIdx.x * blockDim.x + threadIdx.x;
    if (t == 0) g_acc = 0.0;

    if (t < n) {
        const float* xr = x1 + (size_t)t * ROW;
        const float ax = xr[0], ay = xr[1], az = xr[2];
        g_c1[t] = make_float4(ax, ay, az, ax*ax + ay*ay + az*az);

        const int bt = b1[t];
        const int bp = (t == 0) ? -1 : b1[t - 1];
        for (int v = bp + 1; v <= bt; v++) g_bstart[v] = t;
    }
    if (t <= NBATCH) {
        const int blast = b1[n - 1];
        if (t > blast) g_bstart[t] = n;
    }
}

template<int NS>
__device__ __forceinline__ float query_core(
    const float* __restrict__ x1, const float* __restrict__ f2,
    int start, int cnt, float cx, float cy, float cz, int lane)
{
    const float n2q = cx*cx + cy*cy + cz*cz;
    const float m2x = -2.0f*cx, m2y = -2.0f*cy, m2z = -2.0f*cz;

    // ---- distance phase -> packed keys: rounded d2 bits (high 23) | j (low 9) ----
    unsigned keys[NS];
    #pragma unroll
    for (int s = 0; s < NS; s++) {
        const int j = lane + 32 * s;
        float d2 = CUDART_INF_F;
        if (j < cnt) {
            const float4 a = g_c1[start + j];
            float t = fmaf(a.x, m2x, a.w);    // |a|^2 - 2*dot, 3 FMAs
            t = fmaf(a.y, m2y, t);
            t = fmaf(a.z, m2z, t);
            d2 = fmaxf(t + n2q, 0.0f);
        }
        // d2 >= 0 -> order-monotone bits; round to 14 mantissa bits, embed index:
        // keys distinct, exact tie-break by lowest index.
        keys[s] = ((__float_as_uint(d2) + 0x100u) & 0xFFFFFE00u) | (unsigned)j;
    }

    // ---- selection: 8 rounds of (tree-min scan -> redux -> rebias) ----
    unsigned wks[KNN];
    unsigned base = 0;   // true key = keys[s] + base
    #pragma unroll
    for (int k = 0; k < KNN; k++) {
        unsigned m;
        if (NS == 9) {
            const unsigned a = min(min(keys[0], keys[1]), min(keys[2], keys[3]));
            const unsigned b = min(min(keys[4], keys[5]), min(keys[6], keys[7]));
            m = min(min(a, b), keys[8]);
        } else {
            const unsigned m01 = min(keys[0], keys[1]),  m23 = min(keys[2],  keys[3]);
            const unsigned m45 = min(keys[4], keys[5]),  m67 = min(keys[6],  keys[7]);
            const unsigned m89 = min(keys[8], keys[9]),  mAB = min(keys[NS-2], keys[NS-1]);
            m = min(min(min(m01, m23), min(m45, m67)), min(m89, mAB));
        }
        m = redux_min_u32(m);
        wks[k] = m + base;                   // winner true key, all lanes agree

        const unsigned step = m + 1u;        // winner wraps to 0xFFFFFFFF next round
        #pragma unroll
        for (int s = 0; s < NS; s++)
            keys[s] -= step;
        base += step;
    }

    // ---- gather phase: decode winners, 32 batched loads, weighted FMAs ----
    float wsum = 0.0f;
    float o0 = 0.f, o1 = 0.f, o2 = 0.f, o3 = 0.f;
    #pragma unroll
    for (int k = 0; k < KNN; k++) {
        const unsigned wk = wks[k];
        const bool valid = wk < INFKEY;
        const float d2r = __uint_as_float(wk & 0xFFFFFE00u);
        const float wv = valid ? (1.0f / fmaxf(d2r, EPSW)) : 0.0f;  // cnt<K pad: w=0
        const int g = valid ? (start + (int)(wk & 0x1FFu)) : start;
        wsum += wv;

        const float* fr = x1 + (size_t)g * ROW + 3;
        o0 += wv * fr[lane];
        o1 += wv * fr[lane + 32];
        o2 += wv * fr[lane + 64];
        o3 += wv * fr[lane + 96];
    }

    const float inv = 1.0f / wsum;
    const float d0 = o0 * inv - f2[lane];
    const float d1 = o1 * inv - f2[lane + 32];
    const float d2_ = o2 * inv - f2[lane + 64];
    const float d3 = o3 * inv - f2[lane + 96];
    return d0*d0 + d1*d1 + d2_*d2_ + d3*d3;
}

__global__ __launch_bounds__(64) void knn_mse_kernel(
    const float* __restrict__ x1,
    const float* __restrict__ x2,
    const int*   __restrict__ b2,
    float*       __restrict__ out,
    int n)
{
    __shared__ float red[2];

    const int tid  = threadIdx.x;
    const int lane = tid & 31;
    const int wid  = tid >> 5;
    const int q    = blockIdx.x * 2 + wid;   // 2 queries per 64-thread block

    const float* xq = x2 + (size_t)q * ROW;
    const float cx = xq[0], cy = xq[1], cz = xq[2];
    const int b = min(max(b2[q], 0), NBATCH - 1);

    const int start = g_bstart[b];
    const int end   = g_bstart[b + 1];
    int cnt = end - start;
    if (cnt > MAXSLOTS * 32) cnt = MAXSLOTS * 32;   // safety clamp; never fires

    float acc;
    if (cnt <= 9 * 32)
        acc = query_core<9>(x1, xq + 3, start, cnt, cx, cy, cz, lane);
    else
        acc = query_core<MAXSLOTS>(x1, xq + 3, start, cnt, cx, cy, cz, lane);

    // ---- warp reduce -> shared -> one atomic per block; last block finalizes ----
    #pragma unroll
    for (int offr = 16; offr; offr >>= 1)
        acc += __shfl_down_sync(0xffffffffu, acc, offr);
    if (lane == 0) red[wid] = acc;
    __syncthreads();
    if (tid == 0) {
        const float s = red[0] + red[1];
        atomicAdd(&g_acc, (double)s);
        __threadfence();
        const unsigned rank = atomicInc(&g_done, gridDim.x - 1);  // wraps -> self-reset
        if (rank == gridDim.x - 1) {
            out[0] = (float)(g_acc / ((double)n * (double)DIMF));
        }
    }
}

extern "C" void kernel_launch(void* const* d_in, const int* in_sizes, int n_in,
                              void* d_out, int out_size)
{
    const float* x1 = (const float*)d_in[0];
    const float* x2 = (const float*)d_in[1];
    const int*   b1 = (const int*)d_in[2];
    const int*   b2 = (const int*)d_in[3];
    const int n = in_sizes[2];   // N points

    prep_kernel<<<(n + 255) / 256, 256>>>(x1, b1, n);
    knn_mse_kernel<<<n / 2, 64>>>(x1, x2, b2, (float*)d_out, n);
}

// round 16
// speedup vs baseline: 1.0482x; 1.0482x over previous
#include <cuda_runtime.h>
#include <cuda_bf16.h>
#include <math_constants.h>

#define ROW    131     // 3 coords + 128 features
#define DIMF   128
#define KNN    8
#define MAXSLOTS 12    // cnt up to 384 (actual max ~256+5sigma)
#define EPSW   1e-16f
#define NBATCH 1024
#define NMAX   32768
#define INFKEY 0x7F800000u

__device__ double   g_acc;
__device__ unsigned g_done = 0;           // self-resetting via atomicInc wrap
__device__ int      g_bstart[NBATCH + 1];
__device__ float4   g_c1[NMAX];           // (x, y, z, |c|^2)
__device__ float2   g_win[NMAX * KNN];    // per-query winners: (weight, idx-as-float-bits)

__device__ __forceinline__ unsigned redux_min_u32(unsigned v) {
    unsigned r;
    asm("redux.sync.min.u32 %0, %1, 0xffffffff;" : "=r"(r) : "r"(v));
    return r;
}

// Prep: zero accumulator, batch-start table by boundary detection,
// float4 coord repack with precomputed squared norm in .w.
__global__ __launch_bounds__(256) void prep_kernel(
    const float* __restrict__ x1, const int* __restrict__ b1, int n)
{
    const int t = blockIdx.x * blockDim.x + threadIdx.x;
    if (t == 0) g_acc = 0.0;

    if (t < n) {
        const float* xr = x1 + (size_t)t * ROW;
        const float ax = xr[0], ay = xr[1], az = xr[2];
        g_c1[t] = make_float4(ax, ay, az, ax*ax + ay*ay + az*az);

        const int bt = b1[t];
        const int bp = (t == 0) ? -1 : b1[t - 1];
        for (int v = bp + 1; v <= bt; v++) g_bstart[v] = t;
    }
    if (t <= NBATCH) {
        const int blast = b1[n - 1];
        if (t > blast) g_bstart[t] = n;
    }
}

// ---------- Kernel A: distance + top-8 selection, write winners ----------
template<int NS>
__device__ __forceinline__ void select_core(
    int q, int start, int cnt, float cx, float cy, float cz, int lane)
{
    const float n2q = cx*cx + cy*cy + cz*cz;
    const float m2x = -2.0f*cx, m2y = -2.0f*cy, m2z = -2.0f*cz;

    unsigned keys[NS];
    #pragma unroll
    for (int s = 0; s < NS; s++) {
        const int j = lane + 32 * s;
        float d2 = CUDART_INF_F;
        if (j < cnt) {
            const float4 a = g_c1[start + j];
            float t = fmaf(a.x, m2x, a.w);
            t = fmaf(a.y, m2y, t);
            t = fmaf(a.z, m2z, t);
            d2 = fmaxf(t + n2q, 0.0f);
        }
        // d2 >= 0 -> order-monotone bits; round to 14 mantissa bits, embed index:
        // keys distinct, exact tie-break by lowest index.
        keys[s] = ((__float_as_uint(d2) + 0x100u) & 0xFFFFFE00u) | (unsigned)j;
    }

    unsigned base = 0;   // true key = keys[s] + base
    #pragma unroll
    for (int k = 0; k < KNN; k++) {
        unsigned m;
        if (NS == 9) {
            const unsigned a = min(min(keys[0], keys[1]), min(keys[2], keys[3]));
            const unsigned b = min(min(keys[4], keys[5]), min(keys[6], keys[7]));
            m = min(min(a, b), keys[8]);
        } else {
            const unsigned m01 = min(keys[0], keys[1]),  m23 = min(keys[2],  keys[3]);
            const unsigned m45 = min(keys[4], keys[5]),  m67 = min(keys[6],  keys[7]);
            const unsigned m89 = min(keys[8], keys[9]),  mAB = min(keys[NS-2], keys[NS-1]);
            m = min(min(min(m01, m23), min(m45, m67)), min(m89, mAB));
        }
        m = redux_min_u32(m);
        const unsigned wk = m + base;        // winner true key, all lanes agree

        const unsigned step = m + 1u;        // winner wraps to 0xFFFFFFFF next round
        #pragma unroll
        for (int s = 0; s < NS; s++)
            keys[s] -= step;
        base += step;

        // decode in all lanes, lane k stores winner k
        const bool valid = wk < INFKEY;
        const float d2r = __uint_as_float(wk & 0xFFFFFE00u);
        const float wv = valid ? (1.0f / fmaxf(d2r, EPSW)) : 0.0f;  // cnt<K pad: w=0
        const int g = valid ? (start + (int)(wk & 0x1FFu)) : start;
        if (lane == k)
            g_win[q * KNN + k] = make_float2(wv, __int_as_float(g));
    }
}

__global__ __launch_bounds__(128) void select_kernel(
    const float* __restrict__ x2,
    const int*   __restrict__ b2,
    int n)
{
    const int tid  = threadIdx.x;
    const int lane = tid & 31;
    const int wid  = tid >> 5;
    const int q    = blockIdx.x * 4 + wid;

    const float* xq = x2 + (size_t)q * ROW;
    const float cx = xq[0], cy = xq[1], cz = xq[2];
    const int b = min(max(b2[q], 0), NBATCH - 1);

    const int start = g_bstart[b];
    const int end   = g_bstart[b + 1];
    int cnt = end - start;
    if (cnt > MAXSLOTS * 32) cnt = MAXSLOTS * 32;   // safety clamp; never fires

    if (cnt <= 9 * 32)
        select_core<9>(q, start, cnt, cx, cy, cz, lane);
    else
        select_core<MAXSLOTS>(q, start, cnt, cx, cy, cz, lane);
}

// ---------- Kernel B: gather + weighted MSE reduce (pure memory streaming) ----------
__global__ __launch_bounds__(128) void gather_kernel(
    const float* __restrict__ x1,
    const float* __restrict__ x2,
    float*       __restrict__ out,
    int n)
{
    __shared__ float red[4];

    const int tid  = threadIdx.x;
    const int lane = tid & 31;
    const int wid  = tid >> 5;
    const int q    = blockIdx.x * 4 + wid;

    // winners: uniform loads, all lanes (broadcast wavefronts, L2-fresh from A)
    float w[KNN]; int gi[KNN];
    #pragma unroll
    for (int k = 0; k < KNN; k++) {
        const float2 win = g_win[q * KNN + k];
        w[k]  = win.x;
        gi[k] = __float_as_int(win.y);
    }

    float wsum = 0.0f;
    #pragma unroll
    for (int k = 0; k < KNN; k++) wsum += w[k];

    // all 36 loads issue back-to-back: 32 gather + 4 f2 -> max MLP against DRAM
    const float* f2 = x2 + (size_t)q * ROW + 3;
    float o0 = 0.f, o1 = 0.f, o2 = 0.f, o3 = 0.f;
    #pragma unroll
    for (int k = 0; k < KNN; k++) {
        const float* fr = x1 + (size_t)gi[k] * ROW + 3;
        const float wk = w[k];
        o0 += wk * fr[lane];
        o1 += wk * fr[lane + 32];
        o2 += wk * fr[lane + 64];
        o3 += wk * fr[lane + 96];
    }

    const float inv = 1.0f / wsum;
    const float d0 = o0 * inv - f2[lane];
    const float d1 = o1 * inv - f2[lane + 32];
    const float d2 = o2 * inv - f2[lane + 64];
    const float d3 = o3 * inv - f2[lane + 96];
    float acc = d0*d0 + d1*d1 + d2*d2 + d3*d3;

    #pragma unroll
    for (int offr = 16; offr; offr >>= 1)
        acc += __shfl_down_sync(0xffffffffu, acc, offr);
    if (lane == 0) red[wid] = acc;
    __syncthreads();
    if (tid == 0) {
        const float s = red[0] + red[1] + red[2] + red[3];
        atomicAdd(&g_acc, (double)s);
        __threadfence();
        const unsigned rank = atomicInc(&g_done, gridDim.x - 1);  // wraps -> self-reset
        if (rank == gridDim.x - 1) {
            out[0] = (float)(g_acc / ((double)n * (double)DIMF));
        }
    }
}

extern "C" void kernel_launch(void* const* d_in, const int* in_sizes, int n_in,
                              void* d_out, int out_size)
{
    const float* x1 = (const float*)d_in[0];
    const float* x2 = (const float*)d_in[1];
    const int*   b1 = (const int*)d_in[2];
    const int*   b2 = (const int*)d_in[3];
    const int n = in_sizes[2];   // N points

    prep_kernel<<<(n + 255) / 256, 256>>>(x1, b1, n);
    select_kernel<<<n / 4, 128>>>(x2, b2, n);
    gather_kernel<<<n / 4, 128>>>(x1, x2, (float*)d_out, n);
}

// round 17
// speedup vs baseline: 1.2303x; 1.1738x over previous
#include <cuda_runtime.h>
#include <cuda_bf16.h>
#include <math_constants.h>

#define ROW    131     // 3 coords + 128 features
#define DIMF   128
#define KNN    8
#define MAXSLOTS 12    // cnt up to 384 (actual max ~256+5sigma)
#define EPSW   1e-16f
#define NBATCH 1024
#define NMAX   32768
#define INFKEY 0x7F800000u

#define NSM        148
#define BLK_PER_SM 8
#define GRID_MAIN  (NSM * BLK_PER_SM)   // 1184 persistent blocks
#define WARPS_MAIN (GRID_MAIN * 4)

__device__ double   g_acc;
__device__ unsigned g_done = 0;           // self-resetting via atomicInc wrap
__device__ int      g_bstart[NBATCH + 1];
__device__ float4   g_c1[NMAX];           // (x, y, z, |c|^2)

__device__ __forceinline__ unsigned redux_min_u32(unsigned v) {
    unsigned r;
    asm("redux.sync.min.u32 %0, %1, 0xffffffff;" : "=r"(r) : "r"(v));
    return r;
}

// Prep: zero accumulator, batch-start table by boundary detection,
// float4 coord repack with precomputed squared norm in .w.
__global__ __launch_bounds__(256) void prep_kernel(
    const float* __restrict__ x1, const int* __restrict__ b1, int n)
{
    const int t = blockIdx.x * blockDim.x + threadIdx.x;
    if (t == 0) g_acc = 0.0;

    if (t < n) {
        const float* xr = x1 + (size_t)t * ROW;
        const float ax = xr[0], ay = xr[1], az = xr[2];
        g_c1[t] = make_float4(ax, ay, az, ax*ax + ay*ay + az*az);

        const int bt = b1[t];
        const int bp = (t == 0) ? -1 : b1[t - 1];
        for (int v = bp + 1; v <= bt; v++) g_bstart[v] = t;
    }
    if (t <= NBATCH) {
        const int blast = b1[n - 1];
        if (t > blast) g_bstart[t] = n;
    }
}

template<int NS>
__device__ __forceinline__ float query_core(
    const float* __restrict__ x1, const float* __restrict__ f2,
    int start, int cnt, float cx, float cy, float cz, int lane)
{
    const float n2q = cx*cx + cy*cy + cz*cz;
    const float m2x = -2.0f*cx, m2y = -2.0f*cy, m2z = -2.0f*cz;

    // ---- distance phase -> packed keys: rounded d2 bits (high 23) | j (low 9) ----
    unsigned keys[NS];
    #pragma unroll
    for (int s = 0; s < NS; s++) {
        const int j = lane + 32 * s;
        float d2 = CUDART_INF_F;
        if (j < cnt) {
            const float4 a = g_c1[start + j];
            float t = fmaf(a.x, m2x, a.w);    // |a|^2 - 2*dot, 3 FMAs
            t = fmaf(a.y, m2y, t);
            t = fmaf(a.z, m2z, t);
            d2 = fmaxf(t + n2q, 0.0f);
        }
        // d2 >= 0 -> order-monotone bits; round to 14 mantissa bits, embed index:
        // keys distinct, exact tie-break by lowest index.
        keys[s] = ((__float_as_uint(d2) + 0x100u) & 0xFFFFFE00u) | (unsigned)j;
    }

    // ---- selection: 8 rounds of (tree-min scan -> redux -> rebias) ----
    unsigned wks[KNN];
    unsigned base = 0;   // true key = keys[s] + base
    #pragma unroll
    for (int k = 0; k < KNN; k++) {
        unsigned m;
        if (NS == 9) {
            const unsigned a = min(min(keys[0], keys[1]), min(keys[2], keys[3]));
            const unsigned b = min(min(keys[4], keys[5]), min(keys[6], keys[7]));
            m = min(min(a, b), keys[8]);
        } else {
            const unsigned m01 = min(keys[0], keys[1]),  m23 = min(keys[2],  keys[3]);
            const unsigned m45 = min(keys[4], keys[5]),  m67 = min(keys[6],  keys[7]);
            const unsigned m89 = min(keys[8], keys[9]),  mAB = min(keys[NS-2], keys[NS-1]);
            m = min(min(min(m01, m23), min(m45, m67)), min(m89, mAB));
        }
        m = redux_min_u32(m);
        wks[k] = m + base;                   // winner true key, all lanes agree

        const unsigned step = m + 1u;        // winner wraps to 0xFFFFFFFF next round
        #pragma unroll
        for (int s = 0; s < NS; s++)
            keys[s] -= step;
        base += step;
    }

    // ---- gather phase: decode winners, 32 batched loads, weighted FMAs ----
    float wsum = 0.0f;
    float o0 = 0.f, o1 = 0.f, o2 = 0.f, o3 = 0.f;
    #pragma unroll
    for (int k = 0; k < KNN; k++) {
        const unsigned wk = wks[k];
        const bool valid = wk < INFKEY;
        const float d2r = __uint_as_float(wk & 0xFFFFFE00u);
        const float wv = valid ? (1.0f / fmaxf(d2r, EPSW)) : 0.0f;  // cnt<K pad: w=0
        const int g = valid ? (start + (int)(wk & 0x1FFu)) : start;
        wsum += wv;

        const float* fr = x1 + (size_t)g * ROW + 3;
        o0 += wv * fr[lane];
        o1 += wv * fr[lane + 32];
        o2 += wv * fr[lane + 64];
        o3 += wv * fr[lane + 96];
    }

    const float inv = 1.0f / wsum;
    const float d0 = o0 * inv - f2[lane];
    const float d1 = o1 * inv - f2[lane + 32];
    const float d2_ = o2 * inv - f2[lane + 64];
    const float d3 = o3 * inv - f2[lane + 96];
    return d0*d0 + d1*d1 + d2_*d2_ + d3*d3;
}

// Persistent: 1184 blocks x 4 warps grid-stride over all queries. One wave,
// no quantization; per-warp accumulator, one atomic per block at the end.
__global__ __launch_bounds__(128) void knn_mse_kernel(
    const float* __restrict__ x1,
    const float* __restrict__ x2,
    const int*   __restrict__ b2,
    float*       __restrict__ out,
    int n)
{
    __shared__ float red[4];

    const int tid  = threadIdx.x;
    const int lane = tid & 31;
    const int wid  = tid >> 5;
    const int gwid = blockIdx.x * 4 + wid;   // global warp id

    float accw = 0.0f;
    for (int q = gwid; q < n; q += WARPS_MAIN) {
        const float* xq = x2 + (size_t)q * ROW;
        const float cx = xq[0], cy = xq[1], cz = xq[2];
        const int b = min(max(b2[q], 0), NBATCH - 1);

        const int start = g_bstart[b];
        const int end   = g_bstart[b + 1];
        int cnt = end - start;
        if (cnt > MAXSLOTS * 32) cnt = MAXSLOTS * 32;   // safety clamp; never fires

        if (cnt <= 9 * 32)
            accw += query_core<9>(x1, xq + 3, start, cnt, cx, cy, cz, lane);
        else
            accw += query_core<MAXSLOTS>(x1, xq + 3, start, cnt, cx, cy, cz, lane);
    }

    // ---- warp reduce -> shared -> one atomic per block; last block finalizes ----
    #pragma unroll
    for (int offr = 16; offr; offr >>= 1)
        accw += __shfl_down_sync(0xffffffffu, accw, offr);
    if (lane == 0) red[wid] = accw;
    __syncthreads();
    if (tid == 0) {
        const float s = red[0] + red[1] + red[2] + red[3];
        atomicAdd(&g_acc, (double)s);
        __threadfence();
        const unsigned rank = atomicInc(&g_done, gridDim.x - 1);  // wraps -> self-reset
        if (rank == gridDim.x - 1) {
            out[0] = (float)(g_acc / ((double)n * (double)DIMF));
        }
    }
}

extern "C" void kernel_launch(void* const* d_in, const int* in_sizes, int n_in,
                              void* d_out, int out_size)
{
    const float* x1 = (const float*)d_in[0];
    const float* x2 = (const float*)d_in[1];
    const int*   b1 = (const int*)d_in[2];
    const int*   b2 = (const int*)d_in[3];
    const int n = in_sizes[2];   // N points

    prep_kernel<<<(n + 255) / 256, 256>>>(x1, b1, n);
    knn_mse_kernel<<<GRID_MAIN, 128>>>(x1, x2, b2, (float*)d_out, n);
}